// round 14
// baseline (speedup 1.0000x reference)
#include <cuda_runtime.h>

// LSTM_40948218200110: B=4096, T=1024, I=8, H=4 (PyTorch gate order) + FC[H->1].
// R12 = R11 with per-warp PRIVATE smem staging: no __syncthreads anywhere in the
// scan (only per-chunk __syncwarp), so warps drift out of phase and cover each
// other's SHFL(26)/MUFU(16) stall windows instead of stalling in lockstep.
//  - 16 lanes/element, 2048 warps, EPB=4 (grid 1024 x 64) for SM balance.
//  - packed fma.rn.f32x2 x-dot (off chain), scalar 2-tree recurrent dot.
//  - exchange: 4 computed-index width-16 gathers + 3 h butterflies (no SELs).
//  - each warp double-buffers its own pair's x in its own smem region.

#define T_STEPS 1024
#define I_DIM   8
#define EPB     4             // elements per block (2 per warp)
#define BLOCK   64            // 2 warps
#define CH_STEPS 8            // timesteps per chunk
#define NCHUNK  (T_STEPS / CH_STEPS)   // 128

typedef unsigned long long ull;

__device__ __forceinline__ float tanh_fast(float x) {
    float y;
    asm("tanh.approx.f32 %0, %1;" : "=f"(y) : "f"(x));
    return y;
}
__device__ __forceinline__ ull ffma2(ull a, ull b, ull c) {
    ull d;
    asm("fma.rn.f32x2 %0, %1, %2, %3;" : "=l"(d) : "l"(a), "l"(b), "l"(c));
    return d;
}
__device__ __forceinline__ ull pack2(float lo, float hi) {
    ull d;
    asm("mov.b64 %0, {%1, %2};" : "=l"(d) : "f"(lo), "f"(hi));
    return d;
}
__device__ __forceinline__ float hsum2(ull v) {
    float lo, hi;
    asm("mov.b64 {%0, %1}, %2;" : "=f"(lo), "=f"(hi) : "l"(v));
    return lo + hi;
}

__global__ __launch_bounds__(BLOCK) void lstm_kernel(
    const float* __restrict__ x,     // [B, T, I]
    const float* __restrict__ Wih,   // [16, 8]
    const float* __restrict__ Whh,   // [16, 4]
    const float* __restrict__ bih,   // [16]
    const float* __restrict__ bhh,   // [16]
    const float* __restrict__ fcw,   // [1, 4]
    const float* __restrict__ fcb,   // [1]
    float* __restrict__ out,         // [B, 1]
    int B)
{
    // Per warp, per buffer: 8 steps x 4 float4 (per step: e0.lo, e1.lo, e0.hi, e1.hi)
    __shared__ float4 sm[2][2][CH_STEPS * 4];

    const int t    = threadIdx.x;
    const int warp = t >> 5;          // 0..1 — owns element pair `warp`
    const int lane = t & 31;
    const int e    = t >> 4;          // local element 0..3
    const int u    = t & 15;          // lane within 16-group
    const int k    = u & 3;           // hidden unit
    const int r    = u >> 2;          // gate: 0=i,1=f,2=g,3=o
    const int half = e & 1;           // element within the warp's pair
    const int b    = blockIdx.x * EPB + e;

    const int row = r * 4 + k;
    // sigmoid(z)=0.5*tanh(0.5z)+0.5 -> fold 0.5 into weights for i/f/o rows.
    const float s    = (r == 2) ? 1.0f : 0.5f;
    const float actM = (r == 2) ? 1.0f : 0.5f;
    const float actB = (r == 2) ? 0.0f : 0.5f;

    ull wx[4], bia;
    float uh[4];
#pragma unroll
    for (int j = 0; j < 4; j++)
        wx[j] = pack2(s * Wih[row * I_DIM + 2 * j], s * Wih[row * I_DIM + 2 * j + 1]);
    // Recurrent weights permuted so uh[m] multiplies h_{k^m} (butterfly mask m).
#pragma unroll
    for (int m = 0; m < 4; m++)
        uh[m] = s * Whh[row * 4 + (k ^ m)];
    bia = pack2(s * (bih[row] + bhh[row]), 0.0f);

    float hs = 0.f, hx1 = 0.f, hx2 = 0.f, hx3 = 0.f;
    float c = 0.f;
    const unsigned FULL = 0xffffffffu;

    // Staging (warp-private): lane qe=lane>>4 picks pair-element, qq=lane&15 its quad.
    const int qe = lane >> 4, qq = lane & 15;
    const int wslot = (qq >> 1) * 4 + (qq & 1) * 2 + qe;
    const float4* xf4 = reinterpret_cast<const float4*>(x);
    const size_t gbase = (size_t)(blockIdx.x * EPB + warp * 2 + qe) * (T_STEPS * 2) + qq;

    const float4* mybase0 = &sm[0][warp][half];
    const float4* mybase1 = &sm[1][warp][half];

    // Prologue: stage chunk 0 (warp-local).
    sm[0][warp][wslot] = xf4[gbase];
    __syncwarp();

    for (int ck = 0; ck < NCHUNK; ck++) {
        float4 pf;
        const bool more = (ck + 1 < NCHUNK);
        if (more) pf = xf4[gbase + (size_t)(ck + 1) * 16];

        const float4* mb = (ck & 1) ? mybase1 : mybase0;

#pragma unroll
        for (int sI = 0; sI < CH_STEPS; sI++) {
            const ulonglong2 xlo = *reinterpret_cast<const ulonglong2*>(mb + sI * 4);
            const ulonglong2 xhi = *reinterpret_cast<const ulonglong2*>(mb + sI * 4 + 2);

            // x-projection (packed, off the recurrent critical path)
            ull acc = ffma2(wx[0], xlo.x, bia);
            acc = ffma2(wx[1], xlo.y, acc);
            acc = ffma2(wx[2], xhi.x, acc);
            acc = ffma2(wx[3], xhi.y, acc);
            const float xz = hsum2(acc);

            // recurrent dot: two parallel scalar chains
            const float z = fmaf(uh[0], hs, fmaf(uh[1], hx1, xz))
                          + fmaf(uh[2], hx2, uh[3] * hx3);

            const float a = fmaf(tanh_fast(z), actM, actB);

            // all-lanes gather of the unit's four gate activations (width-16)
            const float iv = __shfl_sync(FULL, a, k,      16);
            const float fv = __shfl_sync(FULL, a, k + 4,  16);
            const float gv = __shfl_sync(FULL, a, k + 8,  16);
            const float ov = __shfl_sync(FULL, a, k + 12, 16);

            c  = fmaf(fv, c, iv * gv);
            hs = ov * tanh_fast(c);

            // h butterfly exchange (parallel, masks 1,2,3)
            hx1 = __shfl_xor_sync(FULL, hs, 1);
            hx2 = __shfl_xor_sync(FULL, hs, 2);
            hx3 = __shfl_xor_sync(FULL, hs, 3);
        }

        if (more) sm[(ck + 1) & 1][warp][wslot] = pf;
        __syncwarp();
    }

    // ---- final FC: lane u==0 (r=0,k=0) has hs=h0, hx1=h1, hx2=h2, hx3=h3 ----
    if (u == 0) {
        out[b] = fmaf(hs, fcw[0], fmaf(hx1, fcw[1], fmaf(hx2, fcw[2], fmaf(hx3, fcw[3], fcb[0]))));
    }
}

extern "C" void kernel_launch(void* const* d_in, const int* in_sizes, int n_in,
                              void* d_out, int out_size)
{
    const float* x    = (const float*)d_in[0];
    const float* Wih  = (const float*)d_in[1];
    const float* Whh  = (const float*)d_in[2];
    const float* bih  = (const float*)d_in[3];
    const float* bhh  = (const float*)d_in[4];
    const float* fcw  = (const float*)d_in[5];
    const float* fcb  = (const float*)d_in[6];
    float* out = (float*)d_out;

    const int B = in_sizes[0] / (T_STEPS * I_DIM);   // 4096
    const int grid = B / EPB;                        // 1024 blocks of 2 warps

    lstm_kernel<<<grid, BLOCK>>>(x, Wih, Whh, bih, bhh, fcw, fcb, out, B);
}